// round 14
// baseline (speedup 1.0000x reference)
#include <cuda_runtime.h>
#include <cstdint>
#include <cstddef>

// Problem dims
#define VOCAB 32000
#define EMB   512
#define HID   512
#define BATCH 64
#define S_LEN 512

// ---------------------------------------------------------------------------
// Scratch (no allocation allowed -> __device__ global)
// ---------------------------------------------------------------------------
__device__ float g_xproj[(size_t)BATCH * S_LEN * HID]; // 64 MB scratch

// ---------------------------------------------------------------------------
// Packed f32x2 helpers (Blackwell)
// ---------------------------------------------------------------------------
__device__ __forceinline__ unsigned long long packdup(float v) {
    unsigned long long r;
    asm("mov.b64 %0, {%1, %1};" : "=l"(r) : "f"(v));
    return r;
}
__device__ __forceinline__ void ffma2(unsigned long long& acc,
                                      unsigned long long a,
                                      unsigned long long b) {
    asm("fma.rn.f32x2 %0, %1, %2, %0;" : "+l"(acc) : "l"(a), "l"(b));
}
__device__ __forceinline__ float2 unpack2(unsigned long long v) {
    float2 f;
    asm("mov.b64 {%0, %1}, %2;" : "=f"(f.x), "=f"(f.y) : "l"(v));
    return f;
}

// ---------------------------------------------------------------------------
// Kernel 1: x_proj = gather(emb, tok) @ W_ih^T + (b_ih + b_hh)
// (unchanged from R8/R10/R12)
// ---------------------------------------------------------------------------
__global__ void __launch_bounds__(256, 2)
xproj_kernel(const void* __restrict__ tok_raw,
             const float* __restrict__ emb,
             const float* __restrict__ W_ih,
             const float* __restrict__ b_ih,
             const float* __restrict__ b_hh)
{
    __shared__ float              As[16][128];      // A tile, [k][m]
    __shared__ unsigned long long Bsd[16][128];     // B tile, [k][n], dup {v,v}
    __shared__ int                toks[128];
    __shared__ int                s_tok64;

    const int tid = threadIdx.x;
    const int m0  = blockIdx.y * 128;
    const int n0  = blockIdx.x * 128;

    // int64 tokens (LE) => odd 32-bit words of the first 32 elements all zero.
    if (tid < 32) {
        int wv = ((const int*)tok_raw)[2 * tid + 1];
        unsigned nz = __ballot_sync(0xffffffffu, wv != 0);
        if (tid == 0) s_tok64 = (nz == 0u);
    }
    __syncthreads();

    if (tid < 128) {
        int m = m0 + tid;
        toks[tid] = s_tok64 ? (int)((const long long*)tok_raw)[m]
                            : ((const int*)tok_raw)[m];
    }
    __syncthreads();

    const int ldr_m   = tid & 127;
    const int ldr_seg = (tid >> 7) * 8;
    const float* arow_base = emb  + (size_t)toks[ldr_m] * EMB + ldr_seg;
    const float* brow_base = W_ih + (size_t)(n0 + ldr_m) * EMB + ldr_seg;

    const int ty = tid & 15;   // m sub-tile
    const int tx = tid >> 4;   // n sub-tile

    unsigned long long acc[32];
#pragma unroll
    for (int i = 0; i < 32; i++) acc[i] = 0ull;

    for (int kt = 0; kt < EMB / 16; kt++) {
        const int k0 = kt * 16;
        float4 av0 = *(const float4*)(arow_base + k0);
        float4 av1 = *(const float4*)(arow_base + k0 + 4);
        float4 bv0 = *(const float4*)(brow_base + k0);
        float4 bv1 = *(const float4*)(brow_base + k0 + 4);

        __syncthreads();
        As[ldr_seg + 0][ldr_m] = av0.x;
        As[ldr_seg + 1][ldr_m] = av0.y;
        As[ldr_seg + 2][ldr_m] = av0.z;
        As[ldr_seg + 3][ldr_m] = av0.w;
        As[ldr_seg + 4][ldr_m] = av1.x;
        As[ldr_seg + 5][ldr_m] = av1.y;
        As[ldr_seg + 6][ldr_m] = av1.z;
        As[ldr_seg + 7][ldr_m] = av1.w;
        Bsd[ldr_seg + 0][ldr_m] = packdup(bv0.x);
        Bsd[ldr_seg + 1][ldr_m] = packdup(bv0.y);
        Bsd[ldr_seg + 2][ldr_m] = packdup(bv0.z);
        Bsd[ldr_seg + 3][ldr_m] = packdup(bv0.w);
        Bsd[ldr_seg + 4][ldr_m] = packdup(bv1.x);
        Bsd[ldr_seg + 5][ldr_m] = packdup(bv1.y);
        Bsd[ldr_seg + 6][ldr_m] = packdup(bv1.z);
        Bsd[ldr_seg + 7][ldr_m] = packdup(bv1.w);
        __syncthreads();

#pragma unroll
        for (int kk = 0; kk < 16; kk++) {
            ulonglong2 a01 = *(const ulonglong2*)&As[kk][ty * 8];
            ulonglong2 a23 = *(const ulonglong2*)&As[kk][ty * 8 + 4];
            unsigned long long ap[4] = { a01.x, a01.y, a23.x, a23.y };
            ulonglong2 b01 = *(const ulonglong2*)&Bsd[kk][tx * 8];
            ulonglong2 b23 = *(const ulonglong2*)&Bsd[kk][tx * 8 + 2];
            ulonglong2 b45 = *(const ulonglong2*)&Bsd[kk][tx * 8 + 4];
            ulonglong2 b67 = *(const ulonglong2*)&Bsd[kk][tx * 8 + 6];
            unsigned long long bd[8] = { b01.x, b01.y, b23.x, b23.y,
                                         b45.x, b45.y, b67.x, b67.y };
#pragma unroll
            for (int i2 = 0; i2 < 4; i2++)
#pragma unroll
                for (int j = 0; j < 8; j++)
                    ffma2(acc[i2 * 8 + j], ap[i2], bd[j]);
        }
    }

    float bias[8];
    {
        float4 x0 = *(const float4*)(b_ih + n0 + tx * 8);
        float4 x1 = *(const float4*)(b_ih + n0 + tx * 8 + 4);
        float4 y0 = *(const float4*)(b_hh + n0 + tx * 8);
        float4 y1 = *(const float4*)(b_hh + n0 + tx * 8 + 4);
        bias[0] = x0.x + y0.x;  bias[1] = x0.y + y0.y;
        bias[2] = x0.z + y0.z;  bias[3] = x0.w + y0.w;
        bias[4] = x1.x + y1.x;  bias[5] = x1.y + y1.y;
        bias[6] = x1.z + y1.z;  bias[7] = x1.w + y1.w;
    }
#pragma unroll
    for (int i2 = 0; i2 < 4; i2++) {
        float r0[8], r1[8];
#pragma unroll
        for (int j = 0; j < 8; j++) {
            float2 f = unpack2(acc[i2 * 8 + j]);
            r0[j] = f.x + bias[j];
            r1[j] = f.y + bias[j];
        }
        size_t mg = (size_t)(m0 + ty * 8 + i2 * 2);
        float* o0 = g_xproj + mg * HID + n0 + tx * 8;
        float* o1 = o0 + HID;
        *(float4*)(o0)     = make_float4(r0[0], r0[1], r0[2], r0[3]);
        *(float4*)(o0 + 4) = make_float4(r0[4], r0[5], r0[6], r0[7]);
        *(float4*)(o1)     = make_float4(r1[0], r1[1], r1[2], r1[3]);
        *(float4*)(o1 + 4) = make_float4(r1[4], r1[5], r1[6], r1[7]);
    }
}

// ---------------------------------------------------------------------------
// Kernel 2: recurrence, FULL-ROW decomposition (W rows stationary).
// 16 clusters x 8 CTAs x 256 threads; CTA rank j holds W_hh rows
// [64j,64j+64) x all 512 cols in registers: thread (r = t&63, q = t>>6)
// holds W[64j+r][128q..+128) (128 regs). Per step:
//   P1: wait mbar[cur][q] (the 2 h-chunks this quarter needs; 2KB)
//   P2: quarter-dots for 4 batches (256 FFMA2, broadcast LDS from hbuf)
//   P3: STS quarter-partials -> P4 sync
//   P5: combine 4 quarters + xp -> tanh -> STG out + STS h chunk to stage
//   P6: sync -> P7: 8 warps bulk-send the 1KB h chunk to all 8 CTAs
// The cross-CTA wait now gates only the NEXT step's FMA; tanh/stage/send
// have no remote dependency (the reduce-after-wait serialization is gone).
// ---------------------------------------------------------------------------
#define CSZ 8
#define BG  4
#define KC  64
#define CHUNK_TX 2048        /* 2 chunks x 1024 B per quarter-mbar per use */

__global__ void __cluster_dims__(CSZ, 1, 1) __launch_bounds__(256, 1)
rnn_kernel(const float* __restrict__ W_hh, float* __restrict__ out)
{
    __shared__ __align__(16) float hbuf[2][CSZ][BG][KC];   // [buf][src][b][kk] 16 KB
    __shared__ __align__(16) float qparts[4][KC][BG];      // [q][r][b] 4 KB
    __shared__ __align__(16) float stage[2][BG][KC];       // [buf][b][r] 2 KB
    __shared__ unsigned long long mbar[2][4];              // [buf][quarter]

    const int tid  = threadIdx.x;
    const int w    = tid >> 5;       // warp 0..7 == destination CTA for sends
    const int lane = tid & 31;
    unsigned int rank;
    asm("mov.u32 %0, %%cluster_ctarank;" : "=r"(rank));
    const int batch_base = (blockIdx.x / CSZ) * BG;

    // W rows: thread (r_loc = tid&63, q = tid>>6) holds
    // W_hh[64*rank + r_loc][128q .. 128q+128) as 64 ull.
    const int r_loc = tid & 63;
    const int q     = tid >> 6;
    unsigned long long Wv[64];
    {
        const unsigned long long* wrow = (const unsigned long long*)
            (W_hh + (size_t)(64 * rank + r_loc) * HID + q * 128);
#pragma unroll
        for (int i = 0; i < 64; i++) Wv[i] = wrow[i];
    }

    // h(0) = 0: zero hbuf[0] (first 8 KB)
#pragma unroll
    for (int i = 0; i < 8; i++) ((float*)hbuf)[tid + 256 * i] = 0.0f;

    // mbarriers: init + pre-arm all (buf, quarter)
    unsigned int mb_sa[2][4];
#pragma unroll
    for (int b = 0; b < 2; b++)
#pragma unroll
        for (int m = 0; m < 4; m++)
            mb_sa[b][m] = (unsigned int)__cvta_generic_to_shared(&mbar[b][m]);
    if (tid == 0) {
#pragma unroll
        for (int b = 0; b < 2; b++)
#pragma unroll
            for (int m = 0; m < 4; m++) {
                asm volatile("mbarrier.init.shared.b64 [%0], 1;" :: "r"(mb_sa[b][m]) : "memory");
                asm volatile("mbarrier.arrive.expect_tx.shared.b64 _, [%0], %1;"
                             :: "r"(mb_sa[b][m]), "r"(CHUNK_TX) : "memory");
            }
    }

    // Reduce/output role: thread u -> (rr = u>>2, bb = u&3)
    const int bb = tid & 3;
    const int rr = tid >> 2;
    const float* xp_base  = g_xproj + (size_t)(batch_base + bb) * S_LEN * HID + rank * KC + rr;
    float*       out_base = out     + (size_t)(batch_base + bb) * S_LEN * HID + rank * KC + rr;

    // Send addresses: warp w ships stage (my h chunk) to CTA w's
    // hbuf[buf][myrank], tx on CTA w's mbar[buf][myrank>>1].
    unsigned int dst_ra[2], mb_ra[2];
#pragma unroll
    for (int b = 0; b < 2; b++) {
        unsigned int la = (unsigned int)__cvta_generic_to_shared(&hbuf[b][rank][0][0]);
        unsigned int lm = mb_sa[b][rank >> 1];
        asm("mapa.shared::cluster.u32 %0, %1, %2;" : "=r"(dst_ra[b]) : "r"(la), "r"((unsigned)w));
        asm("mapa.shared::cluster.u32 %0, %1, %2;" : "=r"(mb_ra[b])  : "r"(lm), "r"((unsigned)w));
    }
    const unsigned int stage_sa =
        (unsigned int)__cvta_generic_to_shared(&stage[0][0][0]);

    __syncthreads();
    asm volatile("barrier.cluster.arrive.aligned;" ::: "memory");
    asm volatile("barrier.cluster.wait.aligned;"   ::: "memory");

    // xp prefetch pipeline
    float xpv_cur = __ldg(xp_base);

    for (int s = 0; s < S_LEN; s++) {
        const int cur = s & 1;
        const int nxt = cur ^ 1;

        float xpv_next = 0.0f;
        if (s + 1 < S_LEN) xpv_next = __ldg(xp_base + (size_t)(s + 1) * HID);

        // P1: wait for this quarter's 2 h chunks (skip s=0: hbuf[0] zeroed)
        if (s > 0) {
            const unsigned int mb = mb_sa[cur][q];
            // completions of mbar[buf] before this use:
            //   buf1 used at s=1,3,..: parity = (s>>1)&1
            //   buf0 used at s=2,4,..: parity = ((s>>1)+1)&1
            const unsigned int parity =
                cur ? ((unsigned)(s >> 1) & 1u) : (((unsigned)(s >> 1) + 1u) & 1u);
            unsigned int done;
            asm volatile(
                "{\n\t.reg .pred p;\n\t"
                "mbarrier.try_wait.parity.acquire.cluster.shared::cta.b64 p, [%1], %2;\n\t"
                "selp.b32 %0, 1, 0, p;\n\t}"
                : "=r"(done) : "r"(mb), "r"(parity) : "memory");
            if (!done) {
                asm volatile(
                    "{\n\t.reg .pred P1;\n\t"
                    "WL_%=:\n\t"
                    "mbarrier.try_wait.parity.acquire.cluster.shared::cta.b64 P1, [%0], %1, 0x989680;\n\t"
                    "@P1 bra.uni WD_%=;\n\t"
                    "bra.uni WL_%=;\n\t"
                    "WD_%=:\n\t}"
                    :: "r"(mb), "r"(parity) : "memory");
            }
            // Re-arm this quarter's mbar for its next use (s+2): one thread/quarter
            if (lane == 0 && (w & 1) == 0) {
                asm volatile("mbarrier.arrive.expect_tx.shared.b64 _, [%0], %1;"
                             :: "r"(mb), "r"(CHUNK_TX) : "memory");
            }
        }

        // P2: quarter-dots for 4 batches (broadcast LDS: all lanes same addr)
        float p[BG];
#pragma unroll
        for (int b = 0; b < BG; b++) {
            unsigned long long a0 = 0ull, a1 = 0ull;
            const ulonglong2* h0 = (const ulonglong2*)&hbuf[cur][2 * q][b][0];
#pragma unroll
            for (int i = 0; i < 16; i++) {
                ulonglong2 hv = h0[i];
                ffma2(a0, Wv[2 * i],     hv.x);
                ffma2(a1, Wv[2 * i + 1], hv.y);
            }
            const ulonglong2* h1 = (const ulonglong2*)&hbuf[cur][2 * q + 1][b][0];
#pragma unroll
            for (int i = 0; i < 16; i++) {
                ulonglong2 hv = h1[i];
                ffma2(a0, Wv[32 + 2 * i],     hv.x);
                ffma2(a1, Wv[32 + 2 * i + 1], hv.y);
            }
            unsigned long long sa;
            asm("add.rn.f32x2 %0, %1, %2;" : "=l"(sa) : "l"(a0), "l"(a1));
            float2 f = unpack2(sa);
            p[b] = f.x + f.y;
        }

        // P3: publish quarter-partials
        *(float4*)&qparts[q][r_loc][0] = make_float4(p[0], p[1], p[2], p[3]);
        __syncthreads();   // P4

        // P5: combine quarters + xp, tanh, outputs + stage my h chunk
        {
            float sum = xpv_cur
                      + qparts[0][rr][bb] + qparts[1][rr][bb]
                      + qparts[2][rr][bb] + qparts[3][rr][bb];
            float val = tanhf(sum);
            out_base[(size_t)s * HID] = val;
            if (s == S_LEN - 1) {
                out[(size_t)BATCH * S_LEN * HID +
                    (size_t)(batch_base + bb) * HID + rank * KC + rr] = val;
            }
            stage[nxt][bb][rr] = val;
        }
        __syncthreads();   // P6: stage complete (also fences qparts reuse)

        // P7: broadcast my h chunk to all 8 CTAs (8 warps, 1 KB each)
        if (s + 1 < S_LEN && lane == 0) {
            const unsigned int src_sa = stage_sa + (unsigned)nxt * 1024u;
            asm volatile("fence.proxy.async.shared::cta;" ::: "memory");
            asm volatile(
                "cp.async.bulk.shared::cluster.shared::cta.mbarrier::complete_tx::bytes "
                "[%0], [%1], 1024, [%2];"
                :: "r"(dst_ra[nxt]), "r"(src_sa), "r"(mb_ra[nxt]) : "memory");
        }

        xpv_cur = xpv_next;
    }

    asm volatile("barrier.cluster.arrive.aligned;" ::: "memory");
    asm volatile("barrier.cluster.wait.aligned;"   ::: "memory");
}

// ---------------------------------------------------------------------------
// Launch
// ---------------------------------------------------------------------------
extern "C" void kernel_launch(void* const* d_in, const int* in_sizes, int n_in,
                              void* d_out, int out_size)
{
    const void*  tok  = d_in[0];                 // (B,S) int32 or int64
    const float* emb  = (const float*)d_in[1];   // (V,E)
    const float* W_ih = (const float*)d_in[2];   // (H,E)
    const float* W_hh = (const float*)d_in[3];   // (H,H)
    const float* b_ih = (const float*)d_in[4];   // (H,)
    const float* b_hh = (const float*)d_in[5];   // (H,)
    float* out = (float*)d_out;                  // (B,S,H) outputs ++ (1,B,H) hidden

    dim3 grid_p1(HID / 128, (BATCH * S_LEN) / 128);   // (4, 256)
    xproj_kernel<<<grid_p1, 256>>>(tok, emb, W_ih, b_ih, b_hh);

    rnn_kernel<<<(BATCH / BG) * CSZ, 256>>>(W_hh, out);  // 128 CTAs = 16 clusters
}

// round 15
// speedup vs baseline: 1.0455x; 1.0455x over previous
#include <cuda_runtime.h>
#include <cstdint>
#include <cstddef>

// Problem dims
#define VOCAB 32000
#define EMB   512
#define HID   512
#define BATCH 64
#define S_LEN 512

// ---------------------------------------------------------------------------
// Scratch (no allocation allowed -> __device__ global)
// ---------------------------------------------------------------------------
__device__ float g_xproj[(size_t)BATCH * S_LEN * HID]; // 64 MB scratch

// ---------------------------------------------------------------------------
// Packed f32x2 helpers (Blackwell)
// ---------------------------------------------------------------------------
__device__ __forceinline__ unsigned long long packdup(float v) {
    unsigned long long r;
    asm("mov.b64 %0, {%1, %1};" : "=l"(r) : "f"(v));
    return r;
}
__device__ __forceinline__ void ffma2(unsigned long long& acc,
                                      unsigned long long a,
                                      unsigned long long b) {
    asm("fma.rn.f32x2 %0, %1, %2, %0;" : "+l"(acc) : "l"(a), "l"(b));
}
__device__ __forceinline__ float2 unpack2(unsigned long long v) {
    float2 f;
    asm("mov.b64 {%0, %1}, %2;" : "=f"(f.x), "=f"(f.y) : "l"(v));
    return f;
}

// ---------------------------------------------------------------------------
// Kernel 1: x_proj = gather(emb, tok) @ W_ih^T + (b_ih + b_hh)
// (unchanged from R8/R10/R12)
// ---------------------------------------------------------------------------
__global__ void __launch_bounds__(256, 2)
xproj_kernel(const void* __restrict__ tok_raw,
             const float* __restrict__ emb,
             const float* __restrict__ W_ih,
             const float* __restrict__ b_ih,
             const float* __restrict__ b_hh)
{
    __shared__ float              As[16][128];      // A tile, [k][m]
    __shared__ unsigned long long Bsd[16][128];     // B tile, [k][n], dup {v,v}
    __shared__ int                toks[128];
    __shared__ int                s_tok64;

    const int tid = threadIdx.x;
    const int m0  = blockIdx.y * 128;
    const int n0  = blockIdx.x * 128;

    // int64 tokens (LE) => odd 32-bit words of the first 32 elements all zero.
    if (tid < 32) {
        int wv = ((const int*)tok_raw)[2 * tid + 1];
        unsigned nz = __ballot_sync(0xffffffffu, wv != 0);
        if (tid == 0) s_tok64 = (nz == 0u);
    }
    __syncthreads();

    if (tid < 128) {
        int m = m0 + tid;
        toks[tid] = s_tok64 ? (int)((const long long*)tok_raw)[m]
                            : ((const int*)tok_raw)[m];
    }
    __syncthreads();

    const int ldr_m   = tid & 127;
    const int ldr_seg = (tid >> 7) * 8;
    const float* arow_base = emb  + (size_t)toks[ldr_m] * EMB + ldr_seg;
    const float* brow_base = W_ih + (size_t)(n0 + ldr_m) * EMB + ldr_seg;

    const int ty = tid & 15;   // m sub-tile
    const int tx = tid >> 4;   // n sub-tile

    unsigned long long acc[32];
#pragma unroll
    for (int i = 0; i < 32; i++) acc[i] = 0ull;

    for (int kt = 0; kt < EMB / 16; kt++) {
        const int k0 = kt * 16;
        float4 av0 = *(const float4*)(arow_base + k0);
        float4 av1 = *(const float4*)(arow_base + k0 + 4);
        float4 bv0 = *(const float4*)(brow_base + k0);
        float4 bv1 = *(const float4*)(brow_base + k0 + 4);

        __syncthreads();
        As[ldr_seg + 0][ldr_m] = av0.x;
        As[ldr_seg + 1][ldr_m] = av0.y;
        As[ldr_seg + 2][ldr_m] = av0.z;
        As[ldr_seg + 3][ldr_m] = av0.w;
        As[ldr_seg + 4][ldr_m] = av1.x;
        As[ldr_seg + 5][ldr_m] = av1.y;
        As[ldr_seg + 6][ldr_m] = av1.z;
        As[ldr_seg + 7][ldr_m] = av1.w;
        Bsd[ldr_seg + 0][ldr_m] = packdup(bv0.x);
        Bsd[ldr_seg + 1][ldr_m] = packdup(bv0.y);
        Bsd[ldr_seg + 2][ldr_m] = packdup(bv0.z);
        Bsd[ldr_seg + 3][ldr_m] = packdup(bv0.w);
        Bsd[ldr_seg + 4][ldr_m] = packdup(bv1.x);
        Bsd[ldr_seg + 5][ldr_m] = packdup(bv1.y);
        Bsd[ldr_seg + 6][ldr_m] = packdup(bv1.z);
        Bsd[ldr_seg + 7][ldr_m] = packdup(bv1.w);
        __syncthreads();

#pragma unroll
        for (int kk = 0; kk < 16; kk++) {
            ulonglong2 a01 = *(const ulonglong2*)&As[kk][ty * 8];
            ulonglong2 a23 = *(const ulonglong2*)&As[kk][ty * 8 + 4];
            unsigned long long ap[4] = { a01.x, a01.y, a23.x, a23.y };
            ulonglong2 b01 = *(const ulonglong2*)&Bsd[kk][tx * 8];
            ulonglong2 b23 = *(const ulonglong2*)&Bsd[kk][tx * 8 + 2];
            ulonglong2 b45 = *(const ulonglong2*)&Bsd[kk][tx * 8 + 4];
            ulonglong2 b67 = *(const ulonglong2*)&Bsd[kk][tx * 8 + 6];
            unsigned long long bd[8] = { b01.x, b01.y, b23.x, b23.y,
                                         b45.x, b45.y, b67.x, b67.y };
#pragma unroll
            for (int i2 = 0; i2 < 4; i2++)
#pragma unroll
                for (int j = 0; j < 8; j++)
                    ffma2(acc[i2 * 8 + j], ap[i2], bd[j]);
        }
    }

    float bias[8];
    {
        float4 x0 = *(const float4*)(b_ih + n0 + tx * 8);
        float4 x1 = *(const float4*)(b_ih + n0 + tx * 8 + 4);
        float4 y0 = *(const float4*)(b_hh + n0 + tx * 8);
        float4 y1 = *(const float4*)(b_hh + n0 + tx * 8 + 4);
        bias[0] = x0.x + y0.x;  bias[1] = x0.y + y0.y;
        bias[2] = x0.z + y0.z;  bias[3] = x0.w + y0.w;
        bias[4] = x1.x + y1.x;  bias[5] = x1.y + y1.y;
        bias[6] = x1.z + y1.z;  bias[7] = x1.w + y1.w;
    }
#pragma unroll
    for (int i2 = 0; i2 < 4; i2++) {
        float r0[8], r1[8];
#pragma unroll
        for (int j = 0; j < 8; j++) {
            float2 f = unpack2(acc[i2 * 8 + j]);
            r0[j] = f.x + bias[j];
            r1[j] = f.y + bias[j];
        }
        size_t mg = (size_t)(m0 + ty * 8 + i2 * 2);
        float* o0 = g_xproj + mg * HID + n0 + tx * 8;
        float* o1 = o0 + HID;
        *(float4*)(o0)     = make_float4(r0[0], r0[1], r0[2], r0[3]);
        *(float4*)(o0 + 4) = make_float4(r0[4], r0[5], r0[6], r0[7]);
        *(float4*)(o1)     = make_float4(r1[0], r1[1], r1[2], r1[3]);
        *(float4*)(o1 + 4) = make_float4(r1[4], r1[5], r1[6], r1[7]);
    }
}

// ---------------------------------------------------------------------------
// Kernel 2: recurrence, PULL MODEL.
// 16 clusters x 8 CTAs x 256 threads; col-split as R10 (thread holds W rows
// 64w+lane, +32 over cols [64*rank, 64*rank+64); h chunk self-feeds).
// Per step:
//   compute partials (FMA floor 1024 cyc) -> STS into LOCAL part[cur]
//   -> barrier.cluster.arrive (release) ... wait (acquire, ~380 cyc)
//   -> owner threads (t<64) PULL one float4 per source CTA via
//      ld.shared::cluster (215-cyc DSMEM loads, MLP 8) -> reduce + tanh
//   -> h_own[nxt] + out; one __syncthreads.
// No mbars, no cp.async.bulk engine: the ~2000-cyc push flight is gone.
// ---------------------------------------------------------------------------
#define CSZ 8
#define BG  4
#define KC  64

__global__ void __cluster_dims__(CSZ, 1, 1) __launch_bounds__(256, 1)
rnn_kernel(const float* __restrict__ W_hh, float* __restrict__ out)
{
    __shared__ __align__(16) float part[2][512][BG];   // [buf][row][b] 16 KB
    __shared__ __align__(16) float h_own[2][BG][KC];   // [buf][b][k]   2 KB

    const int tid  = threadIdx.x;
    const int w    = tid >> 5;
    const int lane = tid & 31;
    unsigned int rank;
    asm("mov.u32 %0, %%cluster_ctarank;" : "=r"(rank));
    const int batch_base = (blockIdx.x / CSZ) * BG;

    // W rows 64w+lane and +32, cols [64*rank, +64) — 64 ull in registers
    unsigned long long Wp0[KC / 2], Wp1[KC / 2];
    {
        const unsigned long long* wr0 =
            (const unsigned long long*)(W_hh + (size_t)(64 * w + lane) * HID + rank * KC);
        const unsigned long long* wr1 =
            (const unsigned long long*)(W_hh + (size_t)(64 * w + lane + 32) * HID + rank * KC);
#pragma unroll
        for (int i = 0; i < KC / 2; i++) { Wp0[i] = wr0[i]; Wp1[i] = wr1[i]; }
    }

    ((float*)h_own[0])[tid] = 0.0f;   // h0 = 0

    // Owner role (t < 64): row_local = t; pulls part[buf][64*rank + t][0..4)
    // from every source CTA. Precompute 16 remote addresses (2 bufs x 8 srcs).
    unsigned int dsm[2][CSZ];
    {
        const int row_l = tid & 63;
#pragma unroll
        for (int b = 0; b < 2; b++) {
            unsigned int la = (unsigned int)
                __cvta_generic_to_shared(&part[b][64 * rank + row_l][0]);
#pragma unroll
            for (int src = 0; src < CSZ; src++) {
                asm("mapa.shared::cluster.u32 %0, %1, %2;"
                    : "=r"(dsm[b][src]) : "r"(la), "r"((unsigned)src));
            }
        }
    }

    // xp/out pointers for owner role
    const int row_l = tid & 63;           // owner's local row (t<64 active)
    const float* xp_p[BG];
    float*       out_p[BG];
#pragma unroll
    for (int b = 0; b < BG; b++) {
        xp_p[b]  = g_xproj + (size_t)(batch_base + b) * S_LEN * HID + rank * KC + row_l;
        out_p[b] = out     + (size_t)(batch_base + b) * S_LEN * HID + rank * KC + row_l;
    }

    __syncthreads();
    asm volatile("barrier.cluster.arrive.aligned;" ::: "memory");
    asm volatile("barrier.cluster.wait.aligned;"   ::: "memory");

    // xp prefetch pipeline (owner threads only use it)
    float xpv[BG];
#pragma unroll
    for (int b = 0; b < BG; b++) xpv[b] = (tid < 64) ? __ldg(xp_p[b]) : 0.0f;

    for (int s = 0; s < S_LEN; s++) {
        const int cur = s & 1;
        const int nxt = cur ^ 1;

        // Prefetch next step's xp
        float xpn[BG];
        if (tid < 64 && s + 1 < S_LEN) {
#pragma unroll
            for (int b = 0; b < BG; b++)
                xpn[b] = __ldg(xp_p[b] + (size_t)(s + 1) * HID);
        } else {
#pragma unroll
            for (int b = 0; b < BG; b++) xpn[b] = 0.0f;
        }

        // Partials: 2 rows x 4 batches (one broadcast h LDS feeds both rows)
        float p0[BG], p1[BG];
#pragma unroll
        for (int b = 0; b < BG; b++) {
            unsigned long long a0 = 0ull, a1 = 0ull, c0 = 0ull, c1 = 0ull;
            const ulonglong2* hb = (const ulonglong2*)h_own[cur][b];
#pragma unroll
            for (int i = 0; i < KC / 4; i++) {
                ulonglong2 hv = hb[i];
                ffma2(a0, Wp0[2 * i],     hv.x);
                ffma2(a1, Wp0[2 * i + 1], hv.y);
                ffma2(c0, Wp1[2 * i],     hv.x);
                ffma2(c1, Wp1[2 * i + 1], hv.y);
            }
            unsigned long long sa, sc;
            asm("add.rn.f32x2 %0, %1, %2;" : "=l"(sa) : "l"(a0), "l"(a1));
            asm("add.rn.f32x2 %0, %1, %2;" : "=l"(sc) : "l"(c0), "l"(c1));
            float2 fa = unpack2(sa), fc = unpack2(sc);
            p0[b] = fa.x + fa.y;
            p1[b] = fc.x + fc.y;
        }

        // Local STS of partials (conflict-free STS.128 per quarter-phase)
        *(float4*)&part[cur][64 * w + lane][0]      = make_float4(p0[0], p0[1], p0[2], p0[3]);
        *(float4*)&part[cur][64 * w + lane + 32][0] = make_float4(p1[0], p1[1], p1[2], p1[3]);

        // Cluster rendezvous: release my partials, acquire everyone's
        asm volatile("barrier.cluster.arrive.aligned;" ::: "memory");
        asm volatile("barrier.cluster.wait.aligned;"   ::: "memory");

        // Owner threads pull one float4 per source CTA and reduce
        if (tid < 64) {
            float4 v[CSZ];
#pragma unroll
            for (int src = 0; src < CSZ; src++) {
                asm volatile("ld.shared::cluster.v4.f32 {%0, %1, %2, %3}, [%4];"
                             : "=f"(v[src].x), "=f"(v[src].y),
                               "=f"(v[src].z), "=f"(v[src].w)
                             : "r"(dsm[cur][src]));
            }
            float s0 = xpv[0], s1 = xpv[1], s2 = xpv[2], s3 = xpv[3];
#pragma unroll
            for (int src = 0; src < CSZ; src++) {
                s0 += v[src].x; s1 += v[src].y; s2 += v[src].z; s3 += v[src].w;
            }
            float h0 = tanhf(s0), h1 = tanhf(s1), h2 = tanhf(s2), h3 = tanhf(s3);
            h_own[nxt][0][row_l] = h0;
            h_own[nxt][1][row_l] = h1;
            h_own[nxt][2][row_l] = h2;
            h_own[nxt][3][row_l] = h3;
            out_p[0][(size_t)s * HID] = h0;
            out_p[1][(size_t)s * HID] = h1;
            out_p[2][(size_t)s * HID] = h2;
            out_p[3][(size_t)s * HID] = h3;
            if (s == S_LEN - 1) {
                out[(size_t)BATCH * S_LEN * HID + (size_t)(batch_base + 0) * HID + rank * KC + row_l] = h0;
                out[(size_t)BATCH * S_LEN * HID + (size_t)(batch_base + 1) * HID + rank * KC + row_l] = h1;
                out[(size_t)BATCH * S_LEN * HID + (size_t)(batch_base + 2) * HID + rank * KC + row_l] = h2;
                out[(size_t)BATCH * S_LEN * HID + (size_t)(batch_base + 3) * HID + rank * KC + row_l] = h3;
            }
        }
#pragma unroll
        for (int b = 0; b < BG; b++) xpv[b] = xpn[b];
        __syncthreads();   // publish h_own[nxt] to all warps
    }

    asm volatile("barrier.cluster.arrive.aligned;" ::: "memory");
    asm volatile("barrier.cluster.wait.aligned;"   ::: "memory");
}

// ---------------------------------------------------------------------------
// Launch
// ---------------------------------------------------------------------------
extern "C" void kernel_launch(void* const* d_in, const int* in_sizes, int n_in,
                              void* d_out, int out_size)
{
    const void*  tok  = d_in[0];                 // (B,S) int32 or int64
    const float* emb  = (const float*)d_in[1];   // (V,E)
    const float* W_ih = (const float*)d_in[2];   // (H,E)
    const float* W_hh = (const float*)d_in[3];   // (H,H)
    const float* b_ih = (const float*)d_in[4];   // (H,)
    const float* b_hh = (const float*)d_in[5];   // (H,)
    float* out = (float*)d_out;                  // (B,S,H) outputs ++ (1,B,H) hidden

    dim3 grid_p1(HID / 128, (BATCH * S_LEN) / 128);   // (4, 256)
    xproj_kernel<<<grid_p1, 256>>>(tok, emb, W_ih, b_ih, b_hh);

    rnn_kernel<<<(BATCH / BG) * CSZ, 256>>>(W_hh, out);  // 128 CTAs = 16 clusters
}

// round 16
// speedup vs baseline: 1.2614x; 1.2065x over previous
#include <cuda_runtime.h>
#include <cstdint>
#include <cstddef>

// Problem dims
#define VOCAB 32000
#define EMB   512
#define HID   512
#define BATCH 64
#define S_LEN 512

// ---------------------------------------------------------------------------
// Scratch (no allocation allowed -> __device__ global)
// ---------------------------------------------------------------------------
__device__ float g_xproj[(size_t)BATCH * S_LEN * HID]; // 64 MB scratch

// ---------------------------------------------------------------------------
// Packed f32x2 helpers (Blackwell)
// ---------------------------------------------------------------------------
__device__ __forceinline__ unsigned long long packdup(float v) {
    unsigned long long r;
    asm("mov.b64 %0, {%1, %1};" : "=l"(r) : "f"(v));
    return r;
}
__device__ __forceinline__ void ffma2(unsigned long long& acc,
                                      unsigned long long a,
                                      unsigned long long b) {
    asm("fma.rn.f32x2 %0, %1, %2, %0;" : "+l"(acc) : "l"(a), "l"(b));
}
__device__ __forceinline__ float2 unpack2(unsigned long long v) {
    float2 f;
    asm("mov.b64 {%0, %1}, %2;" : "=f"(f.x), "=f"(f.y) : "l"(v));
    return f;
}

// ---------------------------------------------------------------------------
// Kernel 1: x_proj = gather(emb, tok) @ W_ih^T + (b_ih + b_hh)
// BM=BN=128, BK=16, 256 threads, 8x8/thread, f32x2 FFMA.
// TWO-STAGE smem pipeline: one __syncthreads per k-iter; LDG for tile k+2
// issued during compute of tile k+1 (load latency fully hidden).
// ---------------------------------------------------------------------------
__global__ void __launch_bounds__(256, 2)
xproj_kernel(const void* __restrict__ tok_raw,
             const float* __restrict__ emb,
             const float* __restrict__ W_ih,
             const float* __restrict__ b_ih,
             const float* __restrict__ b_hh)
{
    __shared__ float              As[2][16][128];      // [stage][k][m]
    __shared__ unsigned long long Bsd[2][16][128];     // [stage][k][n] dup {v,v}
    __shared__ int                toks[128];
    __shared__ int                s_tok64;

    const int tid = threadIdx.x;
    const int m0  = blockIdx.y * 128;
    const int n0  = blockIdx.x * 128;

    // int64 tokens (LE) => odd 32-bit words of the first 32 elements all zero.
    if (tid < 32) {
        int wv = ((const int*)tok_raw)[2 * tid + 1];
        unsigned nz = __ballot_sync(0xffffffffu, wv != 0);
        if (tid == 0) s_tok64 = (nz == 0u);
    }
    __syncthreads();

    if (tid < 128) {
        int m = m0 + tid;
        toks[tid] = s_tok64 ? (int)((const long long*)tok_raw)[m]
                            : ((const int*)tok_raw)[m];
    }
    __syncthreads();

    // Loaders: thread t loads row (t&127), k-seg ((t>>7)*8 .. +8)
    const int ldr_m   = tid & 127;
    const int ldr_seg = (tid >> 7) * 8;
    const float* arow_base = emb  + (size_t)toks[ldr_m] * EMB + ldr_seg;
    const float* brow_base = W_ih + (size_t)(n0 + ldr_m) * EMB + ldr_seg;

    const int ty = tid & 15;   // m sub-tile
    const int tx = tid >> 4;   // n sub-tile

    unsigned long long acc[32]; // acc[i2*8+j]: (m=ty*8+2*i2, m+1) x (n=n0+tx*8+j)
#pragma unroll
    for (int i = 0; i < 32; i++) acc[i] = 0ull;

    float4 av0, av1, bv0, bv1;   // in-flight LDG regs

    // Helper macro: store held regs into stage st
#define STS_TILE(st)                                                   \
    do {                                                               \
        As[st][ldr_seg + 0][ldr_m] = av0.x;                            \
        As[st][ldr_seg + 1][ldr_m] = av0.y;                            \
        As[st][ldr_seg + 2][ldr_m] = av0.z;                            \
        As[st][ldr_seg + 3][ldr_m] = av0.w;                            \
        As[st][ldr_seg + 4][ldr_m] = av1.x;                            \
        As[st][ldr_seg + 5][ldr_m] = av1.y;                            \
        As[st][ldr_seg + 6][ldr_m] = av1.z;                            \
        As[st][ldr_seg + 7][ldr_m] = av1.w;                            \
        Bsd[st][ldr_seg + 0][ldr_m] = packdup(bv0.x);                  \
        Bsd[st][ldr_seg + 1][ldr_m] = packdup(bv0.y);                  \
        Bsd[st][ldr_seg + 2][ldr_m] = packdup(bv0.z);                  \
        Bsd[st][ldr_seg + 3][ldr_m] = packdup(bv0.w);                  \
        Bsd[st][ldr_seg + 4][ldr_m] = packdup(bv1.x);                  \
        Bsd[st][ldr_seg + 5][ldr_m] = packdup(bv1.y);                  \
        Bsd[st][ldr_seg + 6][ldr_m] = packdup(bv1.z);                  \
        Bsd[st][ldr_seg + 7][ldr_m] = packdup(bv1.w);                  \
    } while (0)

#define LDG_TILE(kt)                                                   \
    do {                                                               \
        const int _k0 = (kt) * 16;                                     \
        av0 = *(const float4*)(arow_base + _k0);                       \
        av1 = *(const float4*)(arow_base + _k0 + 4);                   \
        bv0 = *(const float4*)(brow_base + _k0);                       \
        bv1 = *(const float4*)(brow_base + _k0 + 4);                   \
    } while (0)

    // Prologue: tile 0 staged, tile 1 in flight
    LDG_TILE(0);
    STS_TILE(0);
    LDG_TILE(1);
    __syncthreads();

    const int NKT = EMB / 16;   // 32
    for (int kt = 0; kt < NKT; kt++) {
        const int st = kt & 1;

        // Compute tile kt from stage st
#pragma unroll
        for (int kk = 0; kk < 16; kk++) {
            ulonglong2 a01 = *(const ulonglong2*)&As[st][kk][ty * 8];
            ulonglong2 a23 = *(const ulonglong2*)&As[st][kk][ty * 8 + 4];
            unsigned long long ap[4] = { a01.x, a01.y, a23.x, a23.y };
            ulonglong2 b01 = *(const ulonglong2*)&Bsd[st][kk][tx * 8];
            ulonglong2 b23 = *(const ulonglong2*)&Bsd[st][kk][tx * 8 + 2];
            ulonglong2 b45 = *(const ulonglong2*)&Bsd[st][kk][tx * 8 + 4];
            ulonglong2 b67 = *(const ulonglong2*)&Bsd[st][kk][tx * 8 + 6];
            unsigned long long bd[8] = { b01.x, b01.y, b23.x, b23.y,
                                         b45.x, b45.y, b67.x, b67.y };
#pragma unroll
            for (int i2 = 0; i2 < 4; i2++)
#pragma unroll
                for (int j = 0; j < 8; j++)
                    ffma2(acc[i2 * 8 + j], ap[i2], bd[j]);
        }

        // Stage tile kt+1 (regs already landed), kick off LDG for kt+2
        if (kt + 1 < NKT) {
            STS_TILE((kt + 1) & 1);
            if (kt + 2 < NKT) LDG_TILE(kt + 2);
            __syncthreads();
        }
    }
#undef STS_TILE
#undef LDG_TILE

    // Epilogue: add (b_ih + b_hh), store
    float bias[8];
    {
        float4 x0 = *(const float4*)(b_ih + n0 + tx * 8);
        float4 x1 = *(const float4*)(b_ih + n0 + tx * 8 + 4);
        float4 y0 = *(const float4*)(b_hh + n0 + tx * 8);
        float4 y1 = *(const float4*)(b_hh + n0 + tx * 8 + 4);
        bias[0] = x0.x + y0.x;  bias[1] = x0.y + y0.y;
        bias[2] = x0.z + y0.z;  bias[3] = x0.w + y0.w;
        bias[4] = x1.x + y1.x;  bias[5] = x1.y + y1.y;
        bias[6] = x1.z + y1.z;  bias[7] = x1.w + y1.w;
    }
#pragma unroll
    for (int i2 = 0; i2 < 4; i2++) {
        float r0[8], r1[8];
#pragma unroll
        for (int j = 0; j < 8; j++) {
            float2 f = unpack2(acc[i2 * 8 + j]);
            r0[j] = f.x + bias[j];
            r1[j] = f.y + bias[j];
        }
        size_t mg = (size_t)(m0 + ty * 8 + i2 * 2);
        float* o0 = g_xproj + mg * HID + n0 + tx * 8;
        float* o1 = o0 + HID;
        *(float4*)(o0)     = make_float4(r0[0], r0[1], r0[2], r0[3]);
        *(float4*)(o0 + 4) = make_float4(r0[4], r0[5], r0[6], r0[7]);
        *(float4*)(o1)     = make_float4(r1[0], r1[1], r1[2], r1[3]);
        *(float4*)(o1 + 4) = make_float4(r1[4], r1[5], r1[6], r1[7]);
    }
}

// ---------------------------------------------------------------------------
// Kernel 2: recurrence — R10 VERBATIM (best known: 256 thr, 2 rows/thread,
// stage + warp-autonomous cp.async.bulk + mbar expect_tx, all-warp wait).
// ---------------------------------------------------------------------------
#define CSZ 8
#define BG  4
#define KC  64
#define STEP_TX 8192              /* 8 slabs x 1024 B per owner per step */

__global__ void __cluster_dims__(CSZ, 1, 1) __launch_bounds__(256, 1)
rnn_kernel(const float* __restrict__ W_hh, float* __restrict__ out)
{
    __shared__ float h_own[2][BG][KC];         // [buf][batch][row] 2 KB
    __shared__ float recv[2][CSZ][256];        // [buf][src][lane*8+j] 8 KB
    __shared__ float stage[2][CSZ][256];       // [buf][warp][lane*8+j] 8 KB
    __shared__ unsigned long long mbar[2];

    const int tid  = threadIdx.x;
    const int w    = tid >> 5;       // warp 0..7  == destination CTA
    const int lane = tid & 31;
    unsigned int rank;
    asm("mov.u32 %0, %%cluster_ctarank;" : "=r"(rank));
    const int batch_base = (blockIdx.x / CSZ) * BG;

    // Two register-resident W rows: r0 = 64w+lane, r1 = r0+32, cols [64*rank,+64)
    unsigned long long Wp0[KC / 2], Wp1[KC / 2];
    {
        const unsigned long long* wr0 =
            (const unsigned long long*)(W_hh + (size_t)(64 * w + lane) * HID + rank * KC);
        const unsigned long long* wr1 =
            (const unsigned long long*)(W_hh + (size_t)(64 * w + lane + 32) * HID + rank * KC);
#pragma unroll
        for (int i = 0; i < KC / 2; i++) { Wp0[i] = wr0[i]; Wp1[i] = wr1[i]; }
    }

    ((float*)h_own[0])[tid] = 0.0f;   // h0 = 0 (256 floats, buffer 0)

    // mbarrier init + pre-arm both slots
    const unsigned int mbar0 = (unsigned int)__cvta_generic_to_shared(&mbar[0]);
    const unsigned int mbar1 = (unsigned int)__cvta_generic_to_shared(&mbar[1]);
    if (tid == 0) {
        asm volatile("mbarrier.init.shared.b64 [%0], 1;" :: "r"(mbar0) : "memory");
        asm volatile("mbarrier.init.shared.b64 [%0], 1;" :: "r"(mbar1) : "memory");
        asm volatile("mbarrier.arrive.expect_tx.shared.b64 _, [%0], %1;"
                     :: "r"(mbar0), "r"(STEP_TX) : "memory");
        asm volatile("mbarrier.arrive.expect_tx.shared.b64 _, [%0], %1;"
                     :: "r"(mbar1), "r"(STEP_TX) : "memory");
    }

    // Reduce-role: thread t -> (rel = t>>2 in [0,64), b = t&3)
    const int rb  = tid & 3;
    const int rel = tid >> 2;
    const int ridx = (rel < 32) ? rel * 8 + rb : (rel - 32) * 8 + 4 + rb;
    const float* xp_base  = g_xproj + (size_t)(batch_base + rb) * S_LEN * HID + rank * KC + rel;
    float*       out_base = out     + (size_t)(batch_base + rb) * S_LEN * HID + rank * KC + rel;

    // Remote addresses: warp w sends its slab to CTA w's recv[buf][rank]
    const unsigned int stage_sa =
        (unsigned int)__cvta_generic_to_shared(&stage[0][0][0]);
    unsigned int dst_ra[2], mb_ra[2];
#pragma unroll
    for (int b = 0; b < 2; b++) {
        unsigned int la = (unsigned int)__cvta_generic_to_shared(&recv[b][rank][0]);
        unsigned int lm = b ? mbar1 : mbar0;
        asm("mapa.shared::cluster.u32 %0, %1, %2;" : "=r"(dst_ra[b]) : "r"(la), "r"((unsigned)w));
        asm("mapa.shared::cluster.u32 %0, %1, %2;" : "=r"(mb_ra[b])  : "r"(lm), "r"((unsigned)w));
    }

    __syncthreads();
    asm volatile("barrier.cluster.arrive.aligned;" ::: "memory");
    asm volatile("barrier.cluster.wait.aligned;"   ::: "memory");

    // xp prefetch pipeline
    float xpv_cur = __ldg(xp_base);

    for (int s = 0; s < S_LEN; s++) {
        const int cur = s & 1;
        const int nxt = cur ^ 1;

        float xpv_next = 0.0f;
        if (s + 1 < S_LEN) xpv_next = __ldg(xp_base + (size_t)(s + 1) * HID);

        // Partials: 2 rows x 4 batches, one h LDS feeds both rows
        float p0[BG], p1[BG];
#pragma unroll
        for (int b = 0; b < BG; b++) {
            unsigned long long a0 = 0ull, a1 = 0ull, c0 = 0ull, c1 = 0ull;
            const ulonglong2* hb = (const ulonglong2*)h_own[cur][b];
#pragma unroll
            for (int i = 0; i < KC / 4; i++) {
                ulonglong2 hv = hb[i];                 // broadcast LDS.128
                ffma2(a0, Wp0[2 * i],     hv.x);
                ffma2(a1, Wp0[2 * i + 1], hv.y);
                ffma2(c0, Wp1[2 * i],     hv.x);
                ffma2(c1, Wp1[2 * i + 1], hv.y);
            }
            unsigned long long sa, sc;
            asm("add.rn.f32x2 %0, %1, %2;" : "=l"(sa) : "l"(a0), "l"(a1));
            asm("add.rn.f32x2 %0, %1, %2;" : "=l"(sc) : "l"(c0), "l"(c1));
            float2 fa = unpack2(sa), fc = unpack2(sc);
            p0[b] = fa.x + fa.y;
            p1[b] = fc.x + fc.y;
        }

        // Stage 32B, warp-autonomous 1KB bulk send to owner CTA w
        *(float4*)&stage[cur][w][lane * 8]     = make_float4(p0[0], p0[1], p0[2], p0[3]);
        *(float4*)&stage[cur][w][lane * 8 + 4] = make_float4(p1[0], p1[1], p1[2], p1[3]);
        __syncwarp();
        if (lane == 0) {
            const unsigned int src_sa =
                stage_sa + (unsigned)cur * (CSZ * 1024u) + (unsigned)w * 1024u;
            asm volatile("fence.proxy.async.shared::cta;" ::: "memory");
            asm volatile(
                "cp.async.bulk.shared::cluster.shared::cta.mbarrier::complete_tx::bytes "
                "[%0], [%1], 1024, [%2];"
                :: "r"(dst_ra[cur]), "r"(src_sa), "r"(mb_ra[cur]) : "memory");
        }

        // Wait for all 8 slabs, re-arm, reduce (all 256 threads, 1 value each)
        {
            const unsigned int mb = cur ? mbar1 : mbar0;
            const unsigned int parity = (unsigned)(s >> 1) & 1u;
            unsigned int done;
            asm volatile(
                "{\n\t.reg .pred p;\n\t"
                "mbarrier.try_wait.parity.acquire.cluster.shared::cta.b64 p, [%1], %2;\n\t"
                "selp.b32 %0, 1, 0, p;\n\t}"
                : "=r"(done) : "r"(mb), "r"(parity) : "memory");
            if (!done) {
                asm volatile(
                    "{\n\t.reg .pred P1;\n\t"
                    "WL_%=:\n\t"
                    "mbarrier.try_wait.parity.acquire.cluster.shared::cta.b64 P1, [%0], %1, 0x989680;\n\t"
                    "@P1 bra.uni WD_%=;\n\t"
                    "bra.uni WL_%=;\n\t"
                    "WD_%=:\n\t}"
                    :: "r"(mb), "r"(parity) : "memory");
            }
            if (tid == 0) {
                asm volatile("mbarrier.arrive.expect_tx.shared.b64 _, [%0], %1;"
                             :: "r"(mb), "r"(STEP_TX) : "memory");
            }

            float sum = xpv_cur;
#pragma unroll
            for (int src = 0; src < CSZ; src++)
                sum += recv[cur][src][ridx];
            float val = tanhf(sum);
            h_own[nxt][rb][rel] = val;
            out_base[(size_t)s * HID] = val;
        }
        xpv_cur = xpv_next;
        __syncthreads();   // publish h_own[nxt]
    }

    // hidden = h_T (final state in buffer S_LEN&1 = 0)
    out[(size_t)BATCH * S_LEN * HID +
        (size_t)(batch_base + rb) * HID + rank * KC + rel] = h_own[S_LEN & 1][rb][rel];

    asm volatile("barrier.cluster.arrive.aligned;" ::: "memory");
    asm volatile("barrier.cluster.wait.aligned;"   ::: "memory");
}

// ---------------------------------------------------------------------------
// Launch
// ---------------------------------------------------------------------------
extern "C" void kernel_launch(void* const* d_in, const int* in_sizes, int n_in,
                              void* d_out, int out_size)
{
    const void*  tok  = d_in[0];                 // (B,S) int32 or int64
    const float* emb  = (const float*)d_in[1];   // (V,E)
    const float* W_ih = (const float*)d_in[2];   // (H,E)
    const float* W_hh = (const float*)d_in[3];   // (H,H)
    const float* b_ih = (const float*)d_in[4];   // (H,)
    const float* b_hh = (const float*)d_in[5];   // (H,)
    float* out = (float*)d_out;                  // (B,S,H) outputs ++ (1,B,H) hidden

    dim3 grid_p1(HID / 128, (BATCH * S_LEN) / 128);   // (4, 256)
    xproj_kernel<<<grid_p1, 256>>>(tok, emb, W_ih, b_ih, b_hh);

    rnn_kernel<<<(BATCH / BG) * CSZ, 256>>>(W_hh, out);  // 128 CTAs = 16 clusters
}